// round 1
// baseline (speedup 1.0000x reference)
#include <cuda_runtime.h>
#include <math.h>

#define Tdim 1024
#define BT   2048   // B*T
#define DM   1024
#define NH   16
#define HD   64
#define KVL  512
#define NE   4
#define DH   4096

// ---------------- scratch (device globals; no runtime allocation) ----------------
__device__ float g_xn  [BT*DM];
__device__ float g_q   [BT*DM];
__device__ float g_lat [BT*KVL];
__device__ float g_k   [BT*DM];
__device__ float g_v   [BT*DM];
__device__ float g_s   [32u*1024u*1024u];  // [B*H, T, T] scores/probs (128MB)
__device__ float g_attn[BT*DM];
__device__ float g_x1  [BT*DM];
__device__ float g_xn2 [BT*DM];
__device__ float g_h   [BT*DH];
__device__ int   g_cnt [NE];
__device__ int   g_idx [NE*BT];

// ---------------- elementwise ----------------
__global__ __launch_bounds__(256) void rmsnorm_kernel(
    const float* __restrict__ x, const float* __restrict__ w, float* __restrict__ out) {
    int row = blockIdx.x, tid = threadIdx.x;
    const float* xr = x + (long)row * DM;
    float ss = 0.f;
    for (int d = tid; d < DM; d += 256) { float v = xr[d]; ss += v * v; }
    __shared__ float red[256];
    red[tid] = ss; __syncthreads();
    for (int s = 128; s > 0; s >>= 1) { if (tid < s) red[tid] += red[tid + s]; __syncthreads(); }
    float scale = rsqrtf(red[0] / DM + 1e-6f);
    for (int d = tid; d < DM; d += 256) out[(long)row * DM + d] = w[d] * xr[d] * scale;
}

__global__ __launch_bounds__(256) void layernorm_kernel(
    float* __restrict__ p, const float* __restrict__ g, const float* __restrict__ b) {
    int row = blockIdx.x, tid = threadIdx.x;
    float* xr = p + (long)row * KVL;
    __shared__ float red[256];
    float s = 0.f;
    for (int d = tid; d < KVL; d += 256) s += xr[d];
    red[tid] = s; __syncthreads();
    for (int k = 128; k > 0; k >>= 1) { if (tid < k) red[tid] += red[tid + k]; __syncthreads(); }
    float mu = red[0] / KVL;
    __syncthreads();
    float vs = 0.f;
    for (int d = tid; d < KVL; d += 256) { float dv = xr[d] - mu; vs += dv * dv; }
    red[tid] = vs; __syncthreads();
    for (int k = 128; k > 0; k >>= 1) { if (tid < k) red[tid] += red[tid + k]; __syncthreads(); }
    float inv = rsqrtf(red[0] / KVL + 1e-5f);
    for (int d = tid; d < KVL; d += 256) xr[d] = (xr[d] - mu) * inv * g[d] + b[d];
}

__global__ __launch_bounds__(256) void rope_kernel(float* __restrict__ p) {
    int id = blockIdx.x * 256 + threadIdx.x;      // BT*NH*32 total
    int row = id >> 9;
    int rem = id & 511;
    int h = rem >> 5, d = rem & 31;
    int t = row & (Tdim - 1);
    float* base = p + (long)row * DM + h * HD + d;
    float x1 = base[0], x2 = base[32];
    float inv = powf(10000.f, -(float)d / 32.f);
    float ang = (float)t * inv;
    float sn = sinf(ang), cs = cosf(ang);
    base[0]  = x1 * cs - x2 * sn;
    base[32] = x1 * sn + x2 * cs;
}

__global__ __launch_bounds__(256) void softmax_kernel(float* __restrict__ S) {
    int bid = blockIdx.x;
    int bh = bid >> 10, q = bid & 1023;
    float* row = S + (long)bh * Tdim * Tdim + (long)q * Tdim;
    int n = q + 1, tid = threadIdx.x;
    __shared__ float red[256];
    float m = -1e30f;
    for (int i = tid; i < n; i += 256) m = fmaxf(m, row[i]);
    red[tid] = m; __syncthreads();
    for (int s = 128; s > 0; s >>= 1) { if (tid < s) red[tid] = fmaxf(red[tid], red[tid + s]); __syncthreads(); }
    m = red[0]; __syncthreads();
    float sum = 0.f;
    for (int i = tid; i < n; i += 256) { float e = __expf(row[i] - m); row[i] = e; sum += e; }
    red[tid] = sum; __syncthreads();
    for (int s = 128; s > 0; s >>= 1) { if (tid < s) red[tid] += red[tid + s]; __syncthreads(); }
    float inv = 1.f / red[0];
    for (int i = tid; i < n; i += 256) row[i] *= inv;
    for (int i = n + tid; i < Tdim; i += 256) row[i] = 0.f;   // zero masked tail for O-GEMM
}

__global__ void zero_cnt_kernel() { if (threadIdx.x < NE) g_cnt[threadIdx.x] = 0; }

__global__ __launch_bounds__(128) void gate_kernel(
    const float* __restrict__ xn2, const float* __restrict__ gw, const float* __restrict__ gb) {
    int row = blockIdx.x, tid = threadIdx.x;
    const float* xr = xn2 + (long)row * DM;
    float a0 = 0.f, a1 = 0.f, a2 = 0.f, a3 = 0.f;
    for (int d = tid; d < DM; d += 128) {
        float xv = xr[d];
        a0 += xv * gw[d]; a1 += xv * gw[DM + d]; a2 += xv * gw[2 * DM + d]; a3 += xv * gw[3 * DM + d];
    }
    __shared__ float red[4][128];
    red[0][tid] = a0; red[1][tid] = a1; red[2][tid] = a2; red[3][tid] = a3;
    __syncthreads();
    for (int s = 64; s > 0; s >>= 1) {
        if (tid < s) { for (int e = 0; e < 4; e++) red[e][tid] += red[e][tid + s]; }
        __syncthreads();
    }
    if (tid == 0) {
        float l0 = red[0][0] + gb[0], l1 = red[1][0] + gb[1];
        float l2 = red[2][0] + gb[2], l3 = red[3][0] + gb[3];
        int best = 0; float bv = l0;
        if (l1 > bv) { bv = l1; best = 1; }
        if (l2 > bv) { bv = l2; best = 2; }
        if (l3 > bv) { bv = l3; best = 3; }
        int pos = atomicAdd(&g_cnt[best], 1);
        g_idx[best * BT + pos] = row;
    }
}

// ---------------- generic SGEMM: C[M,N] = A[M,K] * B[N,K]^T (+bias,+relu,+res) ----------------
// Optional per-expert weight stride (blockIdx.z) and token row-gather via g_idx/g_cnt.
__global__ __launch_bounds__(256) void gemm_tn(
    const float* __restrict__ A, const float* __restrict__ Bw, float* __restrict__ C,
    int M, int N, int K,
    const float* __restrict__ bias, const float* __restrict__ res,
    int relu, int use_idx, long wstride) {
    int e = blockIdx.z;
    const float* Bm = Bw + (long)e * wstride;
    int Mz = M;
    const int* rowmap = nullptr;
    if (use_idx) { Mz = g_cnt[e]; rowmap = g_idx + e * BT; }
    int i0 = blockIdx.y * 64;
    if (i0 >= Mz) return;
    int j0 = blockIdx.x * 64;

    __shared__ float As[16][68];
    __shared__ float Bs[16][68];

    int tid = threadIdx.x;
    int lrow = tid >> 2, lq = tid & 3;
    int posA = i0 + lrow;
    bool avalid = posA < Mz;
    int arow = rowmap ? (avalid ? rowmap[posA] : 0) : posA;
    const float* Ar = A + (long)arow * K + lq * 4;
    const float* Br = Bm + (long)(j0 + lrow) * K + lq * 4;

    int tx = tid & 15, ty = tid >> 4;
    float acc[4][4] = {};

    for (int k0 = 0; k0 < K; k0 += 16) {
        float4 av = avalid ? *(const float4*)(Ar + k0) : make_float4(0.f, 0.f, 0.f, 0.f);
        float4 bv = *(const float4*)(Br + k0);
        __syncthreads();
        As[lq * 4 + 0][lrow] = av.x; As[lq * 4 + 1][lrow] = av.y;
        As[lq * 4 + 2][lrow] = av.z; As[lq * 4 + 3][lrow] = av.w;
        Bs[lq * 4 + 0][lrow] = bv.x; Bs[lq * 4 + 1][lrow] = bv.y;
        Bs[lq * 4 + 2][lrow] = bv.z; Bs[lq * 4 + 3][lrow] = bv.w;
        __syncthreads();
#pragma unroll
        for (int k = 0; k < 16; k++) {
            float a0 = As[k][ty * 4 + 0], a1 = As[k][ty * 4 + 1];
            float a2 = As[k][ty * 4 + 2], a3 = As[k][ty * 4 + 3];
            float b0 = Bs[k][tx * 4 + 0], b1 = Bs[k][tx * 4 + 1];
            float b2 = Bs[k][tx * 4 + 2], b3 = Bs[k][tx * 4 + 3];
            acc[0][0] += a0 * b0; acc[0][1] += a0 * b1; acc[0][2] += a0 * b2; acc[0][3] += a0 * b3;
            acc[1][0] += a1 * b0; acc[1][1] += a1 * b1; acc[1][2] += a1 * b2; acc[1][3] += a1 * b3;
            acc[2][0] += a2 * b0; acc[2][1] += a2 * b1; acc[2][2] += a2 * b2; acc[2][3] += a2 * b3;
            acc[3][0] += a3 * b0; acc[3][1] += a3 * b1; acc[3][2] += a3 * b2; acc[3][3] += a3 * b3;
        }
    }
#pragma unroll
    for (int i = 0; i < 4; i++) {
        int pos = i0 + ty * 4 + i;
        if (pos >= Mz) continue;
        int crow = rowmap ? rowmap[pos] : pos;
        float* Cr = C + (long)crow * N + j0 + tx * 4;
#pragma unroll
        for (int j = 0; j < 4; j++) {
            float v = acc[i][j];
            int col = j0 + tx * 4 + j;
            if (bias) v += bias[(long)e * N + col];
            if (relu) v = fmaxf(v, 0.f);
            if (res)  v += res[(long)crow * N + col];
            Cr[j] = v;
        }
    }
}

// ---------------- attention: S = Q K^T / 8 (per b,h), causal blocks skipped ----------------
__global__ __launch_bounds__(256) void attn_score_kernel(
    const float* __restrict__ Q, const float* __restrict__ Km, float* __restrict__ S) {
    int z = blockIdx.z; int b = z >> 4, h = z & 15;
    int q0 = blockIdx.y * 64, k0 = blockIdx.x * 64;
    if (k0 > q0 + 63) return;               // fully masked block
    const float* Qb = Q + (long)b * Tdim * DM + h * HD;
    const float* Kb = Km + (long)b * Tdim * DM + h * HD;
    float* Sb = g_s + (long)z * Tdim * Tdim;
    (void)S;
    __shared__ float Qs[64][68];
    __shared__ float Ks[64][68];
    int tid = threadIdx.x;
#pragma unroll
    for (int s = 0; s < 4; s++) {
        int it = tid + s * 256;
        int row = it >> 4, c4 = it & 15;
        float4 qv = *(const float4*)(Qb + (long)(q0 + row) * DM + c4 * 4);
        Qs[c4 * 4 + 0][row] = qv.x; Qs[c4 * 4 + 1][row] = qv.y;
        Qs[c4 * 4 + 2][row] = qv.z; Qs[c4 * 4 + 3][row] = qv.w;
        float4 kv = *(const float4*)(Kb + (long)(k0 + row) * DM + c4 * 4);
        Ks[c4 * 4 + 0][row] = kv.x; Ks[c4 * 4 + 1][row] = kv.y;
        Ks[c4 * 4 + 2][row] = kv.z; Ks[c4 * 4 + 3][row] = kv.w;
    }
    __syncthreads();
    int tx = tid & 15, ty = tid >> 4;
    float acc[4][4] = {};
#pragma unroll
    for (int k = 0; k < 64; k++) {
        float a0 = Qs[k][ty * 4 + 0], a1 = Qs[k][ty * 4 + 1];
        float a2 = Qs[k][ty * 4 + 2], a3 = Qs[k][ty * 4 + 3];
        float b0 = Ks[k][tx * 4 + 0], b1 = Ks[k][tx * 4 + 1];
        float b2 = Ks[k][tx * 4 + 2], b3 = Ks[k][tx * 4 + 3];
        acc[0][0] += a0 * b0; acc[0][1] += a0 * b1; acc[0][2] += a0 * b2; acc[0][3] += a0 * b3;
        acc[1][0] += a1 * b0; acc[1][1] += a1 * b1; acc[1][2] += a1 * b2; acc[1][3] += a1 * b3;
        acc[2][0] += a2 * b0; acc[2][1] += a2 * b1; acc[2][2] += a2 * b2; acc[2][3] += a2 * b3;
        acc[3][0] += a3 * b0; acc[3][1] += a3 * b1; acc[3][2] += a3 * b2; acc[3][3] += a3 * b3;
    }
#pragma unroll
    for (int i = 0; i < 4; i++) {
        float* Sr = Sb + (long)(q0 + ty * 4 + i) * Tdim + k0 + tx * 4;
#pragma unroll
        for (int j = 0; j < 4; j++) Sr[j] = acc[i][j] * 0.125f;
    }
}

// ---------------- attention: O = P V (per b,h), skipping fully-masked key blocks ----------------
__global__ __launch_bounds__(256) void attn_out_kernel(
    const float* __restrict__ V, float* __restrict__ O) {
    int z = blockIdx.z; int b = z >> 4, h = z & 15;
    int q0 = blockIdx.y * 64;
    const float* Sb = g_s + (long)z * Tdim * Tdim;
    const float* Vb = V + (long)b * Tdim * DM + h * HD;
    __shared__ float Ps[32][68];
    __shared__ float Vs[32][68];
    int tid = threadIdx.x, tx = tid & 15, ty = tid >> 4;
    float acc[4][4] = {};
    int kend = (q0 + 64 < Tdim) ? (q0 + 64) : Tdim;
    for (int kb = 0; kb < kend; kb += 32) {
        __syncthreads();
#pragma unroll
        for (int s = 0; s < 2; s++) {
            int it = tid + s * 256;           // 512 float4s each tile
            int prow = it >> 3, pc4 = it & 7; // P: 64 q-rows x 8 float4
            float4 pv = *(const float4*)(Sb + (long)(q0 + prow) * Tdim + kb + pc4 * 4);
            Ps[pc4 * 4 + 0][prow] = pv.x; Ps[pc4 * 4 + 1][prow] = pv.y;
            Ps[pc4 * 4 + 2][prow] = pv.z; Ps[pc4 * 4 + 3][prow] = pv.w;
            int vr = it >> 4, vc4 = it & 15;  // V: 32 k-rows x 16 float4
            float4 vv = *(const float4*)(Vb + (long)(kb + vr) * DM + vc4 * 4);
            Vs[vr][vc4 * 4 + 0] = vv.x; Vs[vr][vc4 * 4 + 1] = vv.y;
            Vs[vr][vc4 * 4 + 2] = vv.z; Vs[vr][vc4 * 4 + 3] = vv.w;
        }
        __syncthreads();
#pragma unroll
        for (int k = 0; k < 32; k++) {
            float a0 = Ps[k][ty * 4 + 0], a1 = Ps[k][ty * 4 + 1];
            float a2 = Ps[k][ty * 4 + 2], a3 = Ps[k][ty * 4 + 3];
            float b0 = Vs[k][tx * 4 + 0], b1 = Vs[k][tx * 4 + 1];
            float b2 = Vs[k][tx * 4 + 2], b3 = Vs[k][tx * 4 + 3];
            acc[0][0] += a0 * b0; acc[0][1] += a0 * b1; acc[0][2] += a0 * b2; acc[0][3] += a0 * b3;
            acc[1][0] += a1 * b0; acc[1][1] += a1 * b1; acc[1][2] += a1 * b2; acc[1][3] += a1 * b3;
            acc[2][0] += a2 * b0; acc[2][1] += a2 * b1; acc[2][2] += a2 * b2; acc[2][3] += a2 * b3;
            acc[3][0] += a3 * b0; acc[3][1] += a3 * b1; acc[3][2] += a3 * b2; acc[3][3] += a3 * b3;
        }
    }
#pragma unroll
    for (int i = 0; i < 4; i++) {
        int q = q0 + ty * 4 + i;
        float* Or = O + (long)(b * Tdim + q) * DM + h * HD + tx * 4;
#pragma unroll
        for (int j = 0; j < 4; j++) Or[j] = acc[i][j];
    }
}

// ---------------- launch ----------------
extern "C" void kernel_launch(void* const* d_in, const int* in_sizes, int n_in,
                              void* d_out, int out_size) {
    const float* x       = (const float*)d_in[0];
    const float* norm1_w = (const float*)d_in[1];
    const float* norm2_w = (const float*)d_in[2];
    const float* Wq      = (const float*)d_in[3];
    const float* Wdkv    = (const float*)d_in[4];
    const float* Wuk     = (const float*)d_in[5];
    const float* Wuv     = (const float*)d_in[6];
    const float* Wo      = (const float*)d_in[7];
    const float* ln_g    = (const float*)d_in[8];
    const float* ln_b    = (const float*)d_in[9];
    const float* gate_w  = (const float*)d_in[10];
    const float* gate_b  = (const float*)d_in[11];
    const float* W1      = (const float*)d_in[12];
    const float* b1      = (const float*)d_in[13];
    const float* W2      = (const float*)d_in[14];
    const float* b2      = (const float*)d_in[15];
    float* out = (float*)d_out;

    float *p_xn, *p_q, *p_lat, *p_k, *p_v, *p_attn, *p_x1, *p_xn2, *p_h, *p_s;
    cudaGetSymbolAddress((void**)&p_xn,  g_xn);
    cudaGetSymbolAddress((void**)&p_q,   g_q);
    cudaGetSymbolAddress((void**)&p_lat, g_lat);
    cudaGetSymbolAddress((void**)&p_k,   g_k);
    cudaGetSymbolAddress((void**)&p_v,   g_v);
    cudaGetSymbolAddress((void**)&p_attn,g_attn);
    cudaGetSymbolAddress((void**)&p_x1,  g_x1);
    cudaGetSymbolAddress((void**)&p_xn2, g_xn2);
    cudaGetSymbolAddress((void**)&p_h,   g_h);
    cudaGetSymbolAddress((void**)&p_s,   g_s);

    // 1. xn = rmsnorm(x)
    rmsnorm_kernel<<<BT, 256>>>(x, norm1_w, p_xn);
    // 2. q = xn @ Wq^T
    gemm_tn<<<dim3(16, 32, 1), 256>>>(p_xn, Wq, p_q, BT, DM, DM, nullptr, nullptr, 0, 0, 0);
    // 3. lat = layernorm(xn @ Wdkv^T)
    gemm_tn<<<dim3(8, 32, 1), 256>>>(p_xn, Wdkv, p_lat, BT, KVL, DM, nullptr, nullptr, 0, 0, 0);
    layernorm_kernel<<<BT, 256>>>(p_lat, ln_g, ln_b);
    // 4. k, v
    gemm_tn<<<dim3(16, 32, 1), 256>>>(p_lat, Wuk, p_k, BT, DM, KVL, nullptr, nullptr, 0, 0, 0);
    gemm_tn<<<dim3(16, 32, 1), 256>>>(p_lat, Wuv, p_v, BT, DM, KVL, nullptr, nullptr, 0, 0, 0);
    // 5. RoPE on q, k
    rope_kernel<<<4096, 256>>>(p_q);
    rope_kernel<<<4096, 256>>>(p_k);
    // 6. scores + causal softmax + P·V
    attn_score_kernel<<<dim3(16, 16, 32), 256>>>(p_q, p_k, p_s);
    softmax_kernel<<<32768, 256>>>(p_s);
    attn_out_kernel<<<dim3(1, 16, 32), 256>>>(p_v, p_attn);
    // 7. x1 = x + attn @ Wo^T
    gemm_tn<<<dim3(16, 32, 1), 256>>>(p_attn, Wo, p_x1, BT, DM, DM, nullptr, x, 0, 0, 0);
    // 8. xn2 = rmsnorm(x1)
    rmsnorm_kernel<<<BT, 256>>>(p_x1, norm2_w, p_xn2);
    // 9. gating: top-1 expert per token + bucketing
    zero_cnt_kernel<<<1, 32>>>();
    gate_kernel<<<BT, 128>>>(p_xn2, gate_w, gate_b);
    // 10. MoE expert GEMMs (only selected experts' tokens)
    gemm_tn<<<dim3(64, 32, NE), 256>>>(p_xn2, W1, p_h, BT, DH, DM, b1, nullptr, 1, 1, (long)DH * DM);
    gemm_tn<<<dim3(16, 32, NE), 256>>>(p_h, W2, out, BT, DM, DH, b2, p_x1, 0, 1, (long)DM * DH);
    (void)in_sizes; (void)n_in; (void)out_size;
}

// round 2
// speedup vs baseline: 1.2761x; 1.2761x over previous
#include <cuda_runtime.h>
#include <mma.h>
#include <math.h>

using namespace nvcuda;

#define Tdim 1024
#define BT   2048   // B*T
#define DM   1024
#define NH   16
#define HD   64
#define KVL  512
#define NE   4
#define DH   4096

// ---------------- scratch (device globals; no runtime allocation) ----------------
__device__ float g_xn  [BT*DM];
__device__ float g_q   [BT*DM];
__device__ float g_lat [BT*KVL];
__device__ float g_k   [BT*DM];
__device__ float g_v   [BT*DM];
__device__ float g_s   [32u*1024u*1024u];  // [B*H, T, T] scores/probs (128MB)
__device__ float g_attn[BT*DM];
__device__ float g_x1  [BT*DM];
__device__ float g_xn2 [BT*DM];
__device__ float g_h   [BT*DH];
__device__ int   g_cnt [NE];
__device__ int   g_idx [NE*BT];

// ---------------- elementwise ----------------
__global__ __launch_bounds__(256) void rmsnorm_kernel(
    const float* __restrict__ x, const float* __restrict__ w, float* __restrict__ out) {
    int row = blockIdx.x, tid = threadIdx.x;
    const float* xr = x + (long)row * DM;
    float ss = 0.f;
    for (int d = tid; d < DM; d += 256) { float v = xr[d]; ss += v * v; }
    __shared__ float red[256];
    red[tid] = ss; __syncthreads();
    for (int s = 128; s > 0; s >>= 1) { if (tid < s) red[tid] += red[tid + s]; __syncthreads(); }
    float scale = rsqrtf(red[0] / DM + 1e-6f);
    for (int d = tid; d < DM; d += 256) out[(long)row * DM + d] = w[d] * xr[d] * scale;
}

__global__ __launch_bounds__(256) void layernorm_kernel(
    float* __restrict__ p, const float* __restrict__ g, const float* __restrict__ b) {
    int row = blockIdx.x, tid = threadIdx.x;
    float* xr = p + (long)row * KVL;
    __shared__ float red[256];
    float s = 0.f;
    for (int d = tid; d < KVL; d += 256) s += xr[d];
    red[tid] = s; __syncthreads();
    for (int k = 128; k > 0; k >>= 1) { if (tid < k) red[tid] += red[tid + k]; __syncthreads(); }
    float mu = red[0] / KVL;
    __syncthreads();
    float vs = 0.f;
    for (int d = tid; d < KVL; d += 256) { float dv = xr[d] - mu; vs += dv * dv; }
    red[tid] = vs; __syncthreads();
    for (int k = 128; k > 0; k >>= 1) { if (tid < k) red[tid] += red[tid + k]; __syncthreads(); }
    float inv = rsqrtf(red[0] / KVL + 1e-5f);
    for (int d = tid; d < KVL; d += 256) xr[d] = (xr[d] - mu) * inv * g[d] + b[d];
}

__global__ __launch_bounds__(256) void rope_kernel(float* __restrict__ p) {
    int id = blockIdx.x * 256 + threadIdx.x;      // BT*NH*32 total
    int row = id >> 9;
    int rem = id & 511;
    int h = rem >> 5, d = rem & 31;
    int t = row & (Tdim - 1);
    float* base = p + (long)row * DM + h * HD + d;
    float x1 = base[0], x2 = base[32];
    float inv = powf(10000.f, -(float)d / 32.f);
    float ang = (float)t * inv;
    float sn = sinf(ang), cs = cosf(ang);
    base[0]  = x1 * cs - x2 * sn;
    base[32] = x1 * sn + x2 * cs;
}

__global__ __launch_bounds__(256) void softmax_kernel(float* __restrict__ S) {
    int bid = blockIdx.x;
    int bh = bid >> 10, q = bid & 1023;
    float* row = S + (long)bh * Tdim * Tdim + (long)q * Tdim;
    int n = q + 1, tid = threadIdx.x;
    __shared__ float red[256];
    float m = -1e30f;
    for (int i = tid; i < n; i += 256) m = fmaxf(m, row[i]);
    red[tid] = m; __syncthreads();
    for (int s = 128; s > 0; s >>= 1) { if (tid < s) red[tid] = fmaxf(red[tid], red[tid + s]); __syncthreads(); }
    m = red[0]; __syncthreads();
    float sum = 0.f;
    for (int i = tid; i < n; i += 256) { float e = __expf(row[i] - m); row[i] = e; sum += e; }
    red[tid] = sum; __syncthreads();
    for (int s = 128; s > 0; s >>= 1) { if (tid < s) red[tid] += red[tid + s]; __syncthreads(); }
    float inv = 1.f / red[0];
    for (int i = tid; i < n; i += 256) row[i] *= inv;
    for (int i = n + tid; i < Tdim; i += 256) row[i] = 0.f;   // zero masked tail for O-GEMM
}

__global__ void zero_cnt_kernel() { if (threadIdx.x < NE) g_cnt[threadIdx.x] = 0; }

__global__ __launch_bounds__(128) void gate_kernel(
    const float* __restrict__ xn2, const float* __restrict__ gw, const float* __restrict__ gb) {
    int row = blockIdx.x, tid = threadIdx.x;
    const float* xr = xn2 + (long)row * DM;
    float a0 = 0.f, a1 = 0.f, a2 = 0.f, a3 = 0.f;
    for (int d = tid; d < DM; d += 128) {
        float xv = xr[d];
        a0 += xv * gw[d]; a1 += xv * gw[DM + d]; a2 += xv * gw[2 * DM + d]; a3 += xv * gw[3 * DM + d];
    }
    __shared__ float red[4][128];
    red[0][tid] = a0; red[1][tid] = a1; red[2][tid] = a2; red[3][tid] = a3;
    __syncthreads();
    for (int s = 64; s > 0; s >>= 1) {
        if (tid < s) { for (int e = 0; e < 4; e++) red[e][tid] += red[e][tid + s]; }
        __syncthreads();
    }
    if (tid == 0) {
        float l0 = red[0][0] + gb[0], l1 = red[1][0] + gb[1];
        float l2 = red[2][0] + gb[2], l3 = red[3][0] + gb[3];
        int best = 0; float bv = l0;
        if (l1 > bv) { bv = l1; best = 1; }
        if (l2 > bv) { bv = l2; best = 2; }
        if (l3 > bv) { bv = l3; best = 3; }
        int pos = atomicAdd(&g_cnt[best], 1);
        g_idx[best * BT + pos] = row;
    }
}

// ---------------- tf32 tensor-core GEMM: C[M,N] = A[M,K] * B[N,K]^T ----------------
// Block tile 128x128, 8 warps (2x4), warp tile 64x32, BK=32.
// Optional bias/relu/residual, per-expert weight stride (blockIdx.z), token row-gather.
#define GBM 128
#define GBN 128
#define GBK 32

__global__ __launch_bounds__(256) void gemm_tf32(
    const float* __restrict__ A, const float* __restrict__ Bw, float* __restrict__ C,
    int M, int N, int K,
    const float* __restrict__ bias, const float* __restrict__ res,
    int relu, int use_idx, long wstride) {
    int e = blockIdx.z;
    const float* Bm = Bw + (long)e * wstride;
    int Mz = M;
    const int* rowmap = nullptr;
    if (use_idx) { Mz = g_cnt[e]; rowmap = g_idx + e * BT; }
    int i0 = blockIdx.y * GBM;
    if (i0 >= Mz) return;
    int j0 = blockIdx.x * GBN;

    __shared__ float As[GBM][GBK + 4];
    __shared__ float Bs[GBN][GBK + 4];
    __shared__ float stage[8][16][20];

    int tid = threadIdx.x;
    int warp = tid >> 5, lane = tid & 31;
    int wm = warp >> 2, wn = warp & 3;   // 2 x 4 warps

    // precompute gathered A rows for the 4 load slices
    int arows[4]; bool avalid[4];
#pragma unroll
    for (int it = 0; it < 4; it++) {
        int f = tid + it * 256;
        int r = f >> 3;
        int pos = i0 + r;
        avalid[it] = pos < Mz;
        arows[it] = rowmap ? (avalid[it] ? rowmap[pos] : 0) : pos;
    }

    wmma::fragment<wmma::accumulator, 16, 16, 8, float> acc[4][2];
#pragma unroll
    for (int i = 0; i < 4; i++)
#pragma unroll
        for (int j = 0; j < 2; j++) wmma::fill_fragment(acc[i][j], 0.0f);

    for (int k0 = 0; k0 < K; k0 += GBK) {
        if (k0) __syncthreads();
#pragma unroll
        for (int it = 0; it < 4; it++) {
            int f = tid + it * 256;
            int r = f >> 3, c4 = f & 7;
            float4 av = avalid[it] ? *(const float4*)(A + (long)arows[it] * K + k0 + c4 * 4)
                                   : make_float4(0.f, 0.f, 0.f, 0.f);
            *(float4*)&As[r][c4 * 4] = av;
            float4 bv = *(const float4*)(Bm + (long)(j0 + r) * K + k0 + c4 * 4);
            *(float4*)&Bs[r][c4 * 4] = bv;
        }
        __syncthreads();
#pragma unroll
        for (int kk = 0; kk < 4; kk++) {
            wmma::fragment<wmma::matrix_a, 16, 16, 8, wmma::precision::tf32, wmma::row_major> af[4];
            wmma::fragment<wmma::matrix_b, 16, 16, 8, wmma::precision::tf32, wmma::col_major> bf[2];
#pragma unroll
            for (int i = 0; i < 4; i++) {
                wmma::load_matrix_sync(af[i], &As[wm * 64 + i * 16][kk * 8], GBK + 4);
#pragma unroll
                for (int t = 0; t < af[i].num_elements; t++)
                    af[i].x[t] = wmma::__float_to_tf32(af[i].x[t]);
            }
#pragma unroll
            for (int j = 0; j < 2; j++) {
                wmma::load_matrix_sync(bf[j], &Bs[wn * 32 + j * 16][kk * 8], GBK + 4);
#pragma unroll
                for (int t = 0; t < bf[j].num_elements; t++)
                    bf[j].x[t] = wmma::__float_to_tf32(bf[j].x[t]);
            }
#pragma unroll
            for (int i = 0; i < 4; i++)
#pragma unroll
                for (int j = 0; j < 2; j++)
                    wmma::mma_sync(acc[i][j], af[i], bf[j], acc[i][j]);
        }
    }

    // epilogue: stage each 16x16 tile through smem, apply bias/relu/res, gather-store
#pragma unroll
    for (int i = 0; i < 4; i++) {
#pragma unroll
        for (int j = 0; j < 2; j++) {
            wmma::store_matrix_sync(&stage[warp][0][0], acc[i][j], 20, wmma::mem_row_major);
            __syncwarp();
#pragma unroll
            for (int u = 0; u < 8; u++) {
                int el = lane + u * 32;
                int r = el >> 4, c = el & 15;
                int pos = i0 + wm * 64 + i * 16 + r;
                if (pos < Mz) {
                    int crow = rowmap ? rowmap[pos] : pos;
                    int col = j0 + wn * 32 + j * 16 + c;
                    float v = stage[warp][r][c];
                    if (bias) v += bias[(long)e * N + col];
                    if (relu) v = fmaxf(v, 0.f);
                    if (res)  v += res[(long)crow * N + col];
                    C[(long)crow * N + col] = v;
                }
            }
            __syncwarp();
        }
    }
}

// ---------------- attention: S = Q K^T / 8 (per b,h), causal blocks skipped ----------------
__global__ __launch_bounds__(256) void attn_score_kernel(
    const float* __restrict__ Q, const float* __restrict__ Km) {
    int z = blockIdx.z; int b = z >> 4, h = z & 15;
    int q0 = blockIdx.y * 64, k0 = blockIdx.x * 64;
    if (k0 > q0 + 63) return;               // fully masked block
    const float* Qb = Q + (long)b * Tdim * DM + h * HD;
    const float* Kb = Km + (long)b * Tdim * DM + h * HD;
    float* Sb = g_s + (long)z * Tdim * Tdim;
    __shared__ float Qs[64][68];
    __shared__ float Ks[64][68];
    int tid = threadIdx.x;
#pragma unroll
    for (int s = 0; s < 4; s++) {
        int it = tid + s * 256;
        int row = it >> 4, c4 = it & 15;
        float4 qv = *(const float4*)(Qb + (long)(q0 + row) * DM + c4 * 4);
        Qs[c4 * 4 + 0][row] = qv.x; Qs[c4 * 4 + 1][row] = qv.y;
        Qs[c4 * 4 + 2][row] = qv.z; Qs[c4 * 4 + 3][row] = qv.w;
        float4 kv = *(const float4*)(Kb + (long)(k0 + row) * DM + c4 * 4);
        Ks[c4 * 4 + 0][row] = kv.x; Ks[c4 * 4 + 1][row] = kv.y;
        Ks[c4 * 4 + 2][row] = kv.z; Ks[c4 * 4 + 3][row] = kv.w;
    }
    __syncthreads();
    int tx = tid & 15, ty = tid >> 4;
    float acc[4][4] = {};
#pragma unroll
    for (int k = 0; k < 64; k++) {
        float a0 = Qs[k][ty * 4 + 0], a1 = Qs[k][ty * 4 + 1];
        float a2 = Qs[k][ty * 4 + 2], a3 = Qs[k][ty * 4 + 3];
        float b0 = Ks[k][tx * 4 + 0], b1 = Ks[k][tx * 4 + 1];
        float b2 = Ks[k][tx * 4 + 2], b3 = Ks[k][tx * 4 + 3];
        acc[0][0] += a0 * b0; acc[0][1] += a0 * b1; acc[0][2] += a0 * b2; acc[0][3] += a0 * b3;
        acc[1][0] += a1 * b0; acc[1][1] += a1 * b1; acc[1][2] += a1 * b2; acc[1][3] += a1 * b3;
        acc[2][0] += a2 * b0; acc[2][1] += a2 * b1; acc[2][2] += a2 * b2; acc[2][3] += a2 * b3;
        acc[3][0] += a3 * b0; acc[3][1] += a3 * b1; acc[3][2] += a3 * b2; acc[3][3] += a3 * b3;
    }
#pragma unroll
    for (int i = 0; i < 4; i++) {
        float* Sr = Sb + (long)(q0 + ty * 4 + i) * Tdim + k0 + tx * 4;
#pragma unroll
        for (int j = 0; j < 4; j++) Sr[j] = acc[i][j] * 0.125f;
    }
}

// ---------------- attention: O = P V (per b,h), skipping fully-masked key blocks ----------------
__global__ __launch_bounds__(256) void attn_out_kernel(
    const float* __restrict__ V, float* __restrict__ O) {
    int z = blockIdx.z; int b = z >> 4, h = z & 15;
    int q0 = blockIdx.y * 64;
    const float* Sb = g_s + (long)z * Tdim * Tdim;
    const float* Vb = V + (long)b * Tdim * DM + h * HD;
    __shared__ float Ps[32][68];
    __shared__ float Vs[32][68];
    int tid = threadIdx.x, tx = tid & 15, ty = tid >> 4;
    float acc[4][4] = {};
    int kend = (q0 + 64 < Tdim) ? (q0 + 64) : Tdim;
    for (int kb = 0; kb < kend; kb += 32) {
        __syncthreads();
#pragma unroll
        for (int s = 0; s < 2; s++) {
            int it = tid + s * 256;
            int prow = it >> 3, pc4 = it & 7;
            float4 pv = *(const float4*)(Sb + (long)(q0 + prow) * Tdim + kb + pc4 * 4);
            Ps[pc4 * 4 + 0][prow] = pv.x; Ps[pc4 * 4 + 1][prow] = pv.y;
            Ps[pc4 * 4 + 2][prow] = pv.z; Ps[pc4 * 4 + 3][prow] = pv.w;
            int vr = it >> 4, vc4 = it & 15;
            float4 vv = *(const float4*)(Vb + (long)(kb + vr) * DM + vc4 * 4);
            Vs[vr][vc4 * 4 + 0] = vv.x; Vs[vr][vc4 * 4 + 1] = vv.y;
            Vs[vr][vc4 * 4 + 2] = vv.z; Vs[vr][vc4 * 4 + 3] = vv.w;
        }
        __syncthreads();
#pragma unroll
        for (int k = 0; k < 32; k++) {
            float a0 = Ps[k][ty * 4 + 0], a1 = Ps[k][ty * 4 + 1];
            float a2 = Ps[k][ty * 4 + 2], a3 = Ps[k][ty * 4 + 3];
            float b0 = Vs[k][tx * 4 + 0], b1 = Vs[k][tx * 4 + 1];
            float b2 = Vs[k][tx * 4 + 2], b3 = Vs[k][tx * 4 + 3];
            acc[0][0] += a0 * b0; acc[0][1] += a0 * b1; acc[0][2] += a0 * b2; acc[0][3] += a0 * b3;
            acc[1][0] += a1 * b0; acc[1][1] += a1 * b1; acc[1][2] += a1 * b2; acc[1][3] += a1 * b3;
            acc[2][0] += a2 * b0; acc[2][1] += a2 * b1; acc[2][2] += a2 * b2; acc[2][3] += a2 * b3;
            acc[3][0] += a3 * b0; acc[3][1] += a3 * b1; acc[3][2] += a3 * b2; acc[3][3] += a3 * b3;
        }
    }
#pragma unroll
    for (int i = 0; i < 4; i++) {
        int q = q0 + ty * 4 + i;
        float* Or = O + (long)(b * Tdim + q) * DM + h * HD + tx * 4;
#pragma unroll
        for (int j = 0; j < 4; j++) Or[j] = acc[i][j];
    }
}

// ---------------- launch ----------------
extern "C" void kernel_launch(void* const* d_in, const int* in_sizes, int n_in,
                              void* d_out, int out_size) {
    const float* x       = (const float*)d_in[0];
    const float* norm1_w = (const float*)d_in[1];
    const float* norm2_w = (const float*)d_in[2];
    const float* Wq      = (const float*)d_in[3];
    const float* Wdkv    = (const float*)d_in[4];
    const float* Wuk     = (const float*)d_in[5];
    const float* Wuv     = (const float*)d_in[6];
    const float* Wo      = (const float*)d_in[7];
    const float* ln_g    = (const float*)d_in[8];
    const float* ln_b    = (const float*)d_in[9];
    const float* gate_w  = (const float*)d_in[10];
    const float* gate_b  = (const float*)d_in[11];
    const float* W1      = (const float*)d_in[12];
    const float* b1      = (const float*)d_in[13];
    const float* W2      = (const float*)d_in[14];
    const float* b2      = (const float*)d_in[15];
    float* out = (float*)d_out;

    float *p_xn, *p_q, *p_lat, *p_k, *p_v, *p_attn, *p_x1, *p_xn2, *p_h, *p_s;
    cudaGetSymbolAddress((void**)&p_xn,  g_xn);
    cudaGetSymbolAddress((void**)&p_q,   g_q);
    cudaGetSymbolAddress((void**)&p_lat, g_lat);
    cudaGetSymbolAddress((void**)&p_k,   g_k);
    cudaGetSymbolAddress((void**)&p_v,   g_v);
    cudaGetSymbolAddress((void**)&p_attn,g_attn);
    cudaGetSymbolAddress((void**)&p_x1,  g_x1);
    cudaGetSymbolAddress((void**)&p_xn2, g_xn2);
    cudaGetSymbolAddress((void**)&p_h,   g_h);
    cudaGetSymbolAddress((void**)&p_s,   g_s);

    // 1. xn = rmsnorm(x)
    rmsnorm_kernel<<<BT, 256>>>(x, norm1_w, p_xn);
    // 2. q = xn @ Wq^T
    gemm_tf32<<<dim3(DM/128, BT/128, 1), 256>>>(p_xn, Wq, p_q, BT, DM, DM, nullptr, nullptr, 0, 0, 0);
    // 3. lat = layernorm(xn @ Wdkv^T)
    gemm_tf32<<<dim3(KVL/128, BT/128, 1), 256>>>(p_xn, Wdkv, p_lat, BT, KVL, DM, nullptr, nullptr, 0, 0, 0);
    layernorm_kernel<<<BT, 256>>>(p_lat, ln_g, ln_b);
    // 4. k, v
    gemm_tf32<<<dim3(DM/128, BT/128, 1), 256>>>(p_lat, Wuk, p_k, BT, DM, KVL, nullptr, nullptr, 0, 0, 0);
    gemm_tf32<<<dim3(DM/128, BT/128, 1), 256>>>(p_lat, Wuv, p_v, BT, DM, KVL, nullptr, nullptr, 0, 0, 0);
    // 5. RoPE on q, k
    rope_kernel<<<4096, 256>>>(p_q);
    rope_kernel<<<4096, 256>>>(p_k);
    // 6. scores + causal softmax + P·V
    attn_score_kernel<<<dim3(16, 16, 32), 256>>>(p_q, p_k);
    softmax_kernel<<<32768, 256>>>(p_s);
    attn_out_kernel<<<dim3(1, 16, 32), 256>>>(p_v, p_attn);
    // 7. x1 = x + attn @ Wo^T
    gemm_tf32<<<dim3(DM/128, BT/128, 1), 256>>>(p_attn, Wo, p_x1, BT, DM, DM, nullptr, x, 0, 0, 0);
    // 8. xn2 = rmsnorm(x1)
    rmsnorm_kernel<<<BT, 256>>>(p_x1, norm2_w, p_xn2);
    // 9. gating: top-1 expert per token + bucketing
    zero_cnt_kernel<<<1, 32>>>();
    gate_kernel<<<BT, 128>>>(p_xn2, gate_w, gate_b);
    // 10. MoE expert GEMMs (only selected experts' tokens)
    gemm_tf32<<<dim3(DH/128, BT/128, NE), 256>>>(p_xn2, W1, p_h, BT, DH, DM, b1, nullptr, 1, 1, (long)DH * DM);
    gemm_tf32<<<dim3(DM/128, BT/128, NE), 256>>>(p_h, W2, out, BT, DM, DH, b2, p_x1, 0, 1, (long)DM * DH);
    (void)in_sizes; (void)n_in; (void)out_size;
}

// round 4
// speedup vs baseline: 1.4637x; 1.1470x over previous
#include <cuda_runtime.h>
#include <mma.h>
#include <math.h>

using namespace nvcuda;

#define Tdim 1024
#define BT   2048   // B*T
#define DM   1024
#define NH   16
#define HD   64
#define KVL  512
#define NE   4
#define DH   4096

// ---------------- scratch (device globals; no runtime allocation) ----------------
__device__ float g_xn  [BT*DM];
__device__ float g_q   [BT*DM];
__device__ float g_lat [BT*KVL];
__device__ float g_k   [BT*DM];
__device__ float g_v   [BT*DM];
__device__ float g_attn[BT*DM];
__device__ float g_x1  [BT*DM];
__device__ float g_xn2 [BT*DM];
__device__ float g_h   [BT*DH];
__device__ int   g_cnt [NE];
__device__ int   g_idx [NE*BT];

// ---------------- helpers ----------------
__device__ __forceinline__ unsigned f2tf(float x) {
    unsigned r; asm("cvt.rna.tf32.f32 %0, %1;" : "=r"(r) : "f"(x)); return r;
}
__device__ __forceinline__ void mma_tf32(float* c, const unsigned* a, unsigned b0, unsigned b1) {
    asm volatile(
        "mma.sync.aligned.m16n8k8.row.col.f32.tf32.tf32.f32 "
        "{%0,%1,%2,%3}, {%4,%5,%6,%7}, {%8,%9}, {%0,%1,%2,%3};"
        : "+f"(c[0]), "+f"(c[1]), "+f"(c[2]), "+f"(c[3])
        : "r"(a[0]), "r"(a[1]), "r"(a[2]), "r"(a[3]), "r"(b0), "r"(b1));
}

// ---------------- elementwise ----------------
__global__ __launch_bounds__(256) void rmsnorm_kernel(
    const float* __restrict__ x, const float* __restrict__ w, float* __restrict__ out) {
    int row = blockIdx.x, tid = threadIdx.x;
    const float* xr = x + (long)row * DM;
    float ss = 0.f;
    for (int d = tid; d < DM; d += 256) { float v = xr[d]; ss += v * v; }
    __shared__ float red[256];
    red[tid] = ss; __syncthreads();
    for (int s = 128; s > 0; s >>= 1) { if (tid < s) red[tid] += red[tid + s]; __syncthreads(); }
    float scale = rsqrtf(red[0] / DM + 1e-6f);
    for (int d = tid; d < DM; d += 256) out[(long)row * DM + d] = w[d] * xr[d] * scale;
}

__global__ __launch_bounds__(256) void layernorm_kernel(
    float* __restrict__ p, const float* __restrict__ g, const float* __restrict__ b) {
    int row = blockIdx.x, tid = threadIdx.x;
    float* xr = p + (long)row * KVL;
    __shared__ float red[256];
    float s = 0.f;
    for (int d = tid; d < KVL; d += 256) s += xr[d];
    red[tid] = s; __syncthreads();
    for (int k = 128; k > 0; k >>= 1) { if (tid < k) red[tid] += red[tid + k]; __syncthreads(); }
    float mu = red[0] / KVL;
    __syncthreads();
    float vs = 0.f;
    for (int d = tid; d < KVL; d += 256) { float dv = xr[d] - mu; vs += dv * dv; }
    red[tid] = vs; __syncthreads();
    for (int k = 128; k > 0; k >>= 1) { if (tid < k) red[tid] += red[tid + k]; __syncthreads(); }
    float inv = rsqrtf(red[0] / KVL + 1e-5f);
    for (int d = tid; d < KVL; d += 256) xr[d] = (xr[d] - mu) * inv * g[d] + b[d];
}

__global__ __launch_bounds__(256) void rope_kernel(float* __restrict__ p) {
    int id = blockIdx.x * 256 + threadIdx.x;      // BT*NH*32 total
    int row = id >> 9;
    int rem = id & 511;
    int h = rem >> 5, d = rem & 31;
    int t = row & (Tdim - 1);
    float* base = p + (long)row * DM + h * HD + d;
    float x1 = base[0], x2 = base[32];
    float inv = powf(10000.f, -(float)d / 32.f);
    float ang = (float)t * inv;
    float sn = sinf(ang), cs = cosf(ang);
    base[0]  = x1 * cs - x2 * sn;
    base[32] = x1 * sn + x2 * cs;
}

__global__ void zero_cnt_kernel() { if (threadIdx.x < NE) g_cnt[threadIdx.x] = 0; }

__global__ __launch_bounds__(128) void gate_kernel(
    const float* __restrict__ xn2, const float* __restrict__ gw, const float* __restrict__ gb) {
    int row = blockIdx.x, tid = threadIdx.x;
    const float* xr = xn2 + (long)row * DM;
    float a0 = 0.f, a1 = 0.f, a2 = 0.f, a3 = 0.f;
    for (int d = tid; d < DM; d += 128) {
        float xv = xr[d];
        a0 += xv * gw[d]; a1 += xv * gw[DM + d]; a2 += xv * gw[2 * DM + d]; a3 += xv * gw[3 * DM + d];
    }
    __shared__ float red[4][128];
    red[0][tid] = a0; red[1][tid] = a1; red[2][tid] = a2; red[3][tid] = a3;
    __syncthreads();
    for (int s = 64; s > 0; s >>= 1) {
        if (tid < s) { for (int e = 0; e < 4; e++) red[e][tid] += red[e][tid + s]; }
        __syncthreads();
    }
    if (tid == 0) {
        float l0 = red[0][0] + gb[0], l1 = red[1][0] + gb[1];
        float l2 = red[2][0] + gb[2], l3 = red[3][0] + gb[3];
        int best = 0; float bv = l0;
        if (l1 > bv) { bv = l1; best = 1; }
        if (l2 > bv) { bv = l2; best = 2; }
        if (l3 > bv) { bv = l3; best = 3; }
        int pos = atomicAdd(&g_cnt[best], 1);
        g_idx[best * BT + pos] = row;
    }
}

// ---------------- tf32 tensor-core GEMM: C[M,N] = A[M,K] * B[N,K]^T ----------------
#define GBM 128
#define GBN 128
#define GBK 32

__global__ __launch_bounds__(256) void gemm_tf32(
    const float* __restrict__ A, const float* __restrict__ Bw, float* __restrict__ C,
    int M, int N, int K,
    const float* __restrict__ bias, const float* __restrict__ res,
    int relu, int use_idx, long wstride) {
    int e = blockIdx.z;
    const float* Bm = Bw + (long)e * wstride;
    int Mz = M;
    const int* rowmap = nullptr;
    if (use_idx) { Mz = g_cnt[e]; rowmap = g_idx + e * BT; }
    int i0 = blockIdx.y * GBM;
    if (i0 >= Mz) return;
    int j0 = blockIdx.x * GBN;

    __shared__ float As[GBM][GBK + 4];
    __shared__ float Bs[GBN][GBK + 4];
    __shared__ float stage[8][16][20];

    int tid = threadIdx.x;
    int warp = tid >> 5, lane = tid & 31;
    int wm = warp >> 2, wn = warp & 3;   // 2 x 4 warps

    int arows[4]; bool avalid[4];
#pragma unroll
    for (int it = 0; it < 4; it++) {
        int f = tid + it * 256;
        int r = f >> 3;
        int pos = i0 + r;
        avalid[it] = pos < Mz;
        arows[it] = rowmap ? (avalid[it] ? rowmap[pos] : 0) : pos;
    }

    wmma::fragment<wmma::accumulator, 16, 16, 8, float> acc[4][2];
#pragma unroll
    for (int i = 0; i < 4; i++)
#pragma unroll
        for (int j = 0; j < 2; j++) wmma::fill_fragment(acc[i][j], 0.0f);

    for (int k0 = 0; k0 < K; k0 += GBK) {
        if (k0) __syncthreads();
#pragma unroll
        for (int it = 0; it < 4; it++) {
            int f = tid + it * 256;
            int r = f >> 3, c4 = f & 7;
            float4 av = avalid[it] ? *(const float4*)(A + (long)arows[it] * K + k0 + c4 * 4)
                                   : make_float4(0.f, 0.f, 0.f, 0.f);
            *(float4*)&As[r][c4 * 4] = av;
            float4 bv = *(const float4*)(Bm + (long)(j0 + r) * K + k0 + c4 * 4);
            *(float4*)&Bs[r][c4 * 4] = bv;
        }
        __syncthreads();
#pragma unroll
        for (int kk = 0; kk < 4; kk++) {
            wmma::fragment<wmma::matrix_a, 16, 16, 8, wmma::precision::tf32, wmma::row_major> af[4];
            wmma::fragment<wmma::matrix_b, 16, 16, 8, wmma::precision::tf32, wmma::col_major> bf[2];
#pragma unroll
            for (int i = 0; i < 4; i++) {
                wmma::load_matrix_sync(af[i], &As[wm * 64 + i * 16][kk * 8], GBK + 4);
#pragma unroll
                for (int t = 0; t < af[i].num_elements; t++)
                    af[i].x[t] = wmma::__float_to_tf32(af[i].x[t]);
            }
#pragma unroll
            for (int j = 0; j < 2; j++) {
                wmma::load_matrix_sync(bf[j], &Bs[wn * 32 + j * 16][kk * 8], GBK + 4);
#pragma unroll
                for (int t = 0; t < bf[j].num_elements; t++)
                    bf[j].x[t] = wmma::__float_to_tf32(bf[j].x[t]);
            }
#pragma unroll
            for (int i = 0; i < 4; i++)
#pragma unroll
                for (int j = 0; j < 2; j++)
                    wmma::mma_sync(acc[i][j], af[i], bf[j], acc[i][j]);
        }
    }

#pragma unroll
    for (int i = 0; i < 4; i++) {
#pragma unroll
        for (int j = 0; j < 2; j++) {
            wmma::store_matrix_sync(&stage[warp][0][0], acc[i][j], 20, wmma::mem_row_major);
            __syncwarp();
#pragma unroll
            for (int u = 0; u < 8; u++) {
                int el = lane + u * 32;
                int r = el >> 4, c = el & 15;
                int pos = i0 + wm * 64 + i * 16 + r;
                if (pos < Mz) {
                    int crow = rowmap ? rowmap[pos] : pos;
                    int col = j0 + wn * 32 + j * 16 + c;
                    float v = stage[warp][r][c];
                    if (bias) v += bias[(long)e * N + col];
                    if (relu) v = fmaxf(v, 0.f);
                    if (res)  v += res[(long)crow * N + col];
                    C[(long)crow * N + col] = v;
                }
            }
            __syncwarp();
        }
    }
}

// ---------------- fused flash attention (tf32 mma, online softmax, causal) ----------------
// grid: (T/64, B*NH); 128 threads (4 warps). Each warp owns 16 q-rows.
// Dynamic smem: Ks[64][68] + Vs[64][68] + Ps[64][68] = 52224 bytes.
#define FA_LD 68
#define FA_SMEM (3 * 64 * FA_LD * 4)

__global__ __launch_bounds__(128) void flash_attn_kernel(
    const float* __restrict__ Q, const float* __restrict__ Kg,
    const float* __restrict__ Vg, float* __restrict__ O) {
    extern __shared__ float sm[];
    float* Ks = sm;
    float* Vs = sm + 64 * FA_LD;
    float* Ps = sm + 2 * 64 * FA_LD;   // Q staging, then P staging

    int qt = blockIdx.x;
    int z  = blockIdx.y;
    int b  = z >> 4, h = z & 15;
    int q0 = qt * 64;
    int tid = threadIdx.x, warp = tid >> 5, lane = tid & 31;
    int lg = lane >> 2, lr = lane & 3;

    const float* Qb = Q  + (long)(b * Tdim) * DM + h * HD;
    const float* Kb = Kg + (long)(b * Tdim) * DM + h * HD;
    const float* Vb = Vg + (long)(b * Tdim) * DM + h * HD;

    // stage Q tile, build per-warp A fragments (kept in registers)
    for (int it = tid; it < 64 * 16; it += 128) {
        int r = it >> 4, c4 = it & 15;
        *(float4*)&Ps[r * FA_LD + c4 * 4] = *(const float4*)(Qb + (long)(q0 + r) * DM + c4 * 4);
    }
    __syncthreads();
    unsigned qa[8][4];
    int rlo = warp * 16 + lg;
#pragma unroll
    for (int ks = 0; ks < 8; ks++) {
        qa[ks][0] = f2tf(Ps[(rlo)     * FA_LD + ks * 8 + lr]);
        qa[ks][1] = f2tf(Ps[(rlo + 8) * FA_LD + ks * 8 + lr]);
        qa[ks][2] = f2tf(Ps[(rlo)     * FA_LD + ks * 8 + lr + 4]);
        qa[ks][3] = f2tf(Ps[(rlo + 8) * FA_LD + ks * 8 + lr + 4]);
    }

    float o[8][4];
#pragma unroll
    for (int nf = 0; nf < 8; nf++)
#pragma unroll
        for (int e = 0; e < 4; e++) o[nf][e] = 0.f;
    float m_lo = -1e30f, m_hi = -1e30f, l_lo = 0.f, l_hi = 0.f;

    int row_lo = q0 + warp * 16 + lg;
    int row_hi = row_lo + 8;

    for (int kc = 0; kc <= qt; kc++) {
        __syncthreads();
        for (int it = tid; it < 64 * 16; it += 128) {
            int r = it >> 4, c4 = it & 15;
            *(float4*)&Ks[r * FA_LD + c4 * 4] = *(const float4*)(Kb + (long)(kc * 64 + r) * DM + c4 * 4);
            *(float4*)&Vs[r * FA_LD + c4 * 4] = *(const float4*)(Vb + (long)(kc * 64 + r) * DM + c4 * 4);
        }
        __syncthreads();

        // S = Q K^T (16x64 per warp)
        float s[8][4];
#pragma unroll
        for (int nf = 0; nf < 8; nf++)
#pragma unroll
            for (int e = 0; e < 4; e++) s[nf][e] = 0.f;
#pragma unroll
        for (int ks = 0; ks < 8; ks++) {
#pragma unroll
            for (int nf = 0; nf < 8; nf++) {
                unsigned b0 = f2tf(Ks[(nf * 8 + lg) * FA_LD + ks * 8 + lr]);
                unsigned b1 = f2tf(Ks[(nf * 8 + lg) * FA_LD + ks * 8 + lr + 4]);
                mma_tf32(s[nf], qa[ks], b0, b1);
            }
        }

        // scale + causal mask
        int colbase = kc * 64 + lr * 2;
#pragma unroll
        for (int nf = 0; nf < 8; nf++) {
            int c0 = colbase + nf * 8;
            s[nf][0] = (c0     <= row_lo) ? s[nf][0] * 0.125f : -1e30f;
            s[nf][1] = (c0 + 1 <= row_lo) ? s[nf][1] * 0.125f : -1e30f;
            s[nf][2] = (c0     <= row_hi) ? s[nf][2] * 0.125f : -1e30f;
            s[nf][3] = (c0 + 1 <= row_hi) ? s[nf][3] * 0.125f : -1e30f;
        }

        // chunk row-max
        float cm_lo = -1e30f, cm_hi = -1e30f;
#pragma unroll
        for (int nf = 0; nf < 8; nf++) {
            cm_lo = fmaxf(cm_lo, fmaxf(s[nf][0], s[nf][1]));
            cm_hi = fmaxf(cm_hi, fmaxf(s[nf][2], s[nf][3]));
        }
        cm_lo = fmaxf(cm_lo, __shfl_xor_sync(0xffffffffu, cm_lo, 1));
        cm_lo = fmaxf(cm_lo, __shfl_xor_sync(0xffffffffu, cm_lo, 2));
        cm_hi = fmaxf(cm_hi, __shfl_xor_sync(0xffffffffu, cm_hi, 1));
        cm_hi = fmaxf(cm_hi, __shfl_xor_sync(0xffffffffu, cm_hi, 2));

        float nm_lo = fmaxf(m_lo, cm_lo), nm_hi = fmaxf(m_hi, cm_hi);
        float al_lo = __expf(m_lo - nm_lo), al_hi = __expf(m_hi - nm_hi);
        m_lo = nm_lo; m_hi = nm_hi;

        // P = exp(S - m), partial row sums
        float ps_lo = 0.f, ps_hi = 0.f;
#pragma unroll
        for (int nf = 0; nf < 8; nf++) {
            s[nf][0] = __expf(s[nf][0] - m_lo);
            s[nf][1] = __expf(s[nf][1] - m_lo);
            s[nf][2] = __expf(s[nf][2] - m_hi);
            s[nf][3] = __expf(s[nf][3] - m_hi);
            ps_lo += s[nf][0] + s[nf][1];
            ps_hi += s[nf][2] + s[nf][3];
        }
        ps_lo += __shfl_xor_sync(0xffffffffu, ps_lo, 1);
        ps_lo += __shfl_xor_sync(0xffffffffu, ps_lo, 2);
        ps_hi += __shfl_xor_sync(0xffffffffu, ps_hi, 1);
        ps_hi += __shfl_xor_sync(0xffffffffu, ps_hi, 2);
        l_lo = l_lo * al_lo + ps_lo;
        l_hi = l_hi * al_hi + ps_hi;

        // rescale O accumulators
#pragma unroll
        for (int nf = 0; nf < 8; nf++) {
            o[nf][0] *= al_lo; o[nf][1] *= al_lo;
            o[nf][2] *= al_hi; o[nf][3] *= al_hi;
        }

        // stage P to smem (warp-private rows), reload as A fragments
        int prl = warp * 16 + lg;
#pragma unroll
        for (int nf = 0; nf < 8; nf++) {
            Ps[(prl)     * FA_LD + nf * 8 + lr * 2]     = s[nf][0];
            Ps[(prl)     * FA_LD + nf * 8 + lr * 2 + 1] = s[nf][1];
            Ps[(prl + 8) * FA_LD + nf * 8 + lr * 2]     = s[nf][2];
            Ps[(prl + 8) * FA_LD + nf * 8 + lr * 2 + 1] = s[nf][3];
        }
        __syncwarp();

        // O += P V
#pragma unroll
        for (int ks = 0; ks < 8; ks++) {
            unsigned pa[4];
            pa[0] = f2tf(Ps[(prl)     * FA_LD + ks * 8 + lr]);
            pa[1] = f2tf(Ps[(prl + 8) * FA_LD + ks * 8 + lr]);
            pa[2] = f2tf(Ps[(prl)     * FA_LD + ks * 8 + lr + 4]);
            pa[3] = f2tf(Ps[(prl + 8) * FA_LD + ks * 8 + lr + 4]);
#pragma unroll
            for (int nf = 0; nf < 8; nf++) {
                unsigned b0 = f2tf(Vs[(ks * 8 + lr)     * FA_LD + nf * 8 + lg]);
                unsigned b1 = f2tf(Vs[(ks * 8 + lr + 4) * FA_LD + nf * 8 + lg]);
                mma_tf32(o[nf], pa, b0, b1);
            }
        }
    }

    // epilogue: normalize and store
    float inv_lo = 1.f / l_lo, inv_hi = 1.f / l_hi;
    long out_lo = (long)(b * Tdim + row_lo) * DM + h * HD;
    long out_hi = (long)(b * Tdim + row_hi) * DM + h * HD;
#pragma unroll
    for (int nf = 0; nf < 8; nf++) {
        int c = nf * 8 + lr * 2;
        float2 vlo = make_float2(o[nf][0] * inv_lo, o[nf][1] * inv_lo);
        float2 vhi = make_float2(o[nf][2] * inv_hi, o[nf][3] * inv_hi);
        *(float2*)&O[out_lo + c] = vlo;
        *(float2*)&O[out_hi + c] = vhi;
    }
}

// ---------------- launch ----------------
extern "C" void kernel_launch(void* const* d_in, const int* in_sizes, int n_in,
                              void* d_out, int out_size) {
    const float* x       = (const float*)d_in[0];
    const float* norm1_w = (const float*)d_in[1];
    const float* norm2_w = (const float*)d_in[2];
    const float* Wq      = (const float*)d_in[3];
    const float* Wdkv    = (const float*)d_in[4];
    const float* Wuk     = (const float*)d_in[5];
    const float* Wuv     = (const float*)d_in[6];
    const float* Wo      = (const float*)d_in[7];
    const float* ln_g    = (const float*)d_in[8];
    const float* ln_b    = (const float*)d_in[9];
    const float* gate_w  = (const float*)d_in[10];
    const float* gate_b  = (const float*)d_in[11];
    const float* W1      = (const float*)d_in[12];
    const float* b1      = (const float*)d_in[13];
    const float* W2      = (const float*)d_in[14];
    const float* b2      = (const float*)d_in[15];
    float* out = (float*)d_out;

    float *p_xn, *p_q, *p_lat, *p_k, *p_v, *p_attn, *p_x1, *p_xn2, *p_h;
    cudaGetSymbolAddress((void**)&p_xn,  g_xn);
    cudaGetSymbolAddress((void**)&p_q,   g_q);
    cudaGetSymbolAddress((void**)&p_lat, g_lat);
    cudaGetSymbolAddress((void**)&p_k,   g_k);
    cudaGetSymbolAddress((void**)&p_v,   g_v);
    cudaGetSymbolAddress((void**)&p_attn,g_attn);
    cudaGetSymbolAddress((void**)&p_x1,  g_x1);
    cudaGetSymbolAddress((void**)&p_xn2, g_xn2);
    cudaGetSymbolAddress((void**)&p_h,   g_h);

    cudaFuncSetAttribute(flash_attn_kernel, cudaFuncAttributeMaxDynamicSharedMemorySize, FA_SMEM);

    // 1. xn = rmsnorm(x)
    rmsnorm_kernel<<<BT, 256>>>(x, norm1_w, p_xn);
    // 2. q = xn @ Wq^T
    gemm_tf32<<<dim3(DM/128, BT/128, 1), 256>>>(p_xn, Wq, p_q, BT, DM, DM, nullptr, nullptr, 0, 0, 0);
    // 3. lat = layernorm(xn @ Wdkv^T)
    gemm_tf32<<<dim3(KVL/128, BT/128, 1), 256>>>(p_xn, Wdkv, p_lat, BT, KVL, DM, nullptr, nullptr, 0, 0, 0);
    layernorm_kernel<<<BT, 256>>>(p_lat, ln_g, ln_b);
    // 4. k, v
    gemm_tf32<<<dim3(DM/128, BT/128, 1), 256>>>(p_lat, Wuk, p_k, BT, DM, KVL, nullptr, nullptr, 0, 0, 0);
    gemm_tf32<<<dim3(DM/128, BT/128, 1), 256>>>(p_lat, Wuv, p_v, BT, DM, KVL, nullptr, nullptr, 0, 0, 0);
    // 5. RoPE on q, k
    rope_kernel<<<4096, 256>>>(p_q);
    rope_kernel<<<4096, 256>>>(p_k);
    // 6. fused flash attention
    flash_attn_kernel<<<dim3(Tdim/64, 32), 128, FA_SMEM>>>(p_q, p_k, p_v, p_attn);
    // 7. x1 = x + attn @ Wo^T
    gemm_tf32<<<dim3(DM/128, BT/128, 1), 256>>>(p_attn, Wo, p_x1, BT, DM, DM, nullptr, x, 0, 0, 0);
    // 8. xn2 = rmsnorm(x1)
    rmsnorm_kernel<<<BT, 256>>>(p_x1, norm2_w, p_xn2);
    // 9. gating
    zero_cnt_kernel<<<1, 32>>>();
    gate_kernel<<<BT, 128>>>(p_xn2, gate_w, gate_b);
    // 10. MoE expert GEMMs
    gemm_tf32<<<dim3(DH/128, BT/128, NE), 256>>>(p_xn2, W1, p_h, BT, DH, DM, b1, nullptr, 1, 1, (long)DH * DM);
    gemm_tf32<<<dim3(DM/128, BT/128, NE), 256>>>(p_h, W2, out, BT, DM, DH, b2, p_x1, 0, 1, (long)DM * DH);
    (void)in_sizes; (void)n_in; (void)out_size;
}

// round 5
// speedup vs baseline: 2.7615x; 1.8866x over previous
#include <cuda_runtime.h>
#include <math.h>

#define Tdim 1024
#define BT   2048   // B*T
#define DM   1024
#define NH   16
#define HD   64
#define KVL  512
#define NE   4
#define DH   4096

// ---------------- scratch (device globals; no runtime allocation) ----------------
__device__ float g_xn  [BT*DM];
__device__ float g_q   [BT*DM];
__device__ float g_lat [BT*KVL];
__device__ float g_k   [BT*DM];
__device__ float g_v   [BT*DM];
__device__ float g_attn[BT*DM];
__device__ float g_x1  [BT*DM];
__device__ float g_xn2 [BT*DM];
__device__ float g_h   [BT*DH];
__device__ int   g_cnt [NE];
__device__ int   g_idx [NE*BT];

// ---------------- helpers ----------------
__device__ __forceinline__ unsigned f2tf(float x) {
    unsigned r; asm("cvt.rna.tf32.f32 %0, %1;" : "=r"(r) : "f"(x)); return r;
}
__device__ __forceinline__ void mma_tf32(float* c, const unsigned* a, unsigned b0, unsigned b1) {
    asm volatile(
        "mma.sync.aligned.m16n8k8.row.col.f32.tf32.tf32.f32 "
        "{%0,%1,%2,%3}, {%4,%5,%6,%7}, {%8,%9}, {%0,%1,%2,%3};"
        : "+f"(c[0]), "+f"(c[1]), "+f"(c[2]), "+f"(c[3])
        : "r"(a[0]), "r"(a[1]), "r"(a[2]), "r"(a[3]), "r"(b0), "r"(b1));
}
__device__ __forceinline__ void cp_async16(unsigned dst, const void* src, int srcbytes) {
    asm volatile("cp.async.cg.shared.global [%0], [%1], 16, %2;"
                 :: "r"(dst), "l"(src), "r"(srcbytes));
}
__device__ __forceinline__ void cp_commit() { asm volatile("cp.async.commit_group;"); }
__device__ __forceinline__ void cp_wait0()  { asm volatile("cp.async.wait_group 0;"); }

// ---------------- elementwise ----------------
__global__ __launch_bounds__(256) void rmsnorm_kernel(
    const float* __restrict__ x, const float* __restrict__ w, float* __restrict__ out) {
    int row = blockIdx.x, tid = threadIdx.x;
    const float* xr = x + (long)row * DM;
    float ss = 0.f;
    for (int d = tid; d < DM; d += 256) { float v = xr[d]; ss += v * v; }
    __shared__ float red[256];
    red[tid] = ss; __syncthreads();
    for (int s = 128; s > 0; s >>= 1) { if (tid < s) red[tid] += red[tid + s]; __syncthreads(); }
    float scale = rsqrtf(red[0] / DM + 1e-6f);
    for (int d = tid; d < DM; d += 256) out[(long)row * DM + d] = w[d] * xr[d] * scale;
}

__global__ __launch_bounds__(256) void layernorm_kernel(
    float* __restrict__ p, const float* __restrict__ g, const float* __restrict__ b) {
    int row = blockIdx.x, tid = threadIdx.x;
    float* xr = p + (long)row * KVL;
    __shared__ float red[256];
    float s = 0.f;
    for (int d = tid; d < KVL; d += 256) s += xr[d];
    red[tid] = s; __syncthreads();
    for (int k = 128; k > 0; k >>= 1) { if (tid < k) red[tid] += red[tid + k]; __syncthreads(); }
    float mu = red[0] / KVL;
    __syncthreads();
    float vs = 0.f;
    for (int d = tid; d < KVL; d += 256) { float dv = xr[d] - mu; vs += dv * dv; }
    red[tid] = vs; __syncthreads();
    for (int k = 128; k > 0; k >>= 1) { if (tid < k) red[tid] += red[tid + k]; __syncthreads(); }
    float inv = rsqrtf(red[0] / KVL + 1e-5f);
    for (int d = tid; d < KVL; d += 256) xr[d] = (xr[d] - mu) * inv * g[d] + b[d];
}

__global__ __launch_bounds__(256) void rope_kernel(float* __restrict__ p) {
    int id = blockIdx.x * 256 + threadIdx.x;      // BT*NH*32 total
    int row = id >> 9;
    int rem = id & 511;
    int h = rem >> 5, d = rem & 31;
    int t = row & (Tdim - 1);
    float* base = p + (long)row * DM + h * HD + d;
    float x1 = base[0], x2 = base[32];
    float inv = powf(10000.f, -(float)d / 32.f);
    float ang = (float)t * inv;
    float sn = sinf(ang), cs = cosf(ang);
    base[0]  = x1 * cs - x2 * sn;
    base[32] = x1 * sn + x2 * cs;
}

__global__ void zero_cnt_kernel() { if (threadIdx.x < NE) g_cnt[threadIdx.x] = 0; }

__global__ __launch_bounds__(128) void gate_kernel(
    const float* __restrict__ xn2, const float* __restrict__ gw, const float* __restrict__ gb) {
    int row = blockIdx.x, tid = threadIdx.x;
    const float* xr = xn2 + (long)row * DM;
    float a0 = 0.f, a1 = 0.f, a2 = 0.f, a3 = 0.f;
    for (int d = tid; d < DM; d += 128) {
        float xv = xr[d];
        a0 += xv * gw[d]; a1 += xv * gw[DM + d]; a2 += xv * gw[2 * DM + d]; a3 += xv * gw[3 * DM + d];
    }
    __shared__ float red[4][128];
    red[0][tid] = a0; red[1][tid] = a1; red[2][tid] = a2; red[3][tid] = a3;
    __syncthreads();
    for (int s = 64; s > 0; s >>= 1) {
        if (tid < s) { for (int e = 0; e < 4; e++) red[e][tid] += red[e][tid + s]; }
        __syncthreads();
    }
    if (tid == 0) {
        float l0 = red[0][0] + gb[0], l1 = red[1][0] + gb[1];
        float l2 = red[2][0] + gb[2], l3 = red[3][0] + gb[3];
        int best = 0; float bv = l0;
        if (l1 > bv) { bv = l1; best = 1; }
        if (l2 > bv) { bv = l2; best = 2; }
        if (l3 > bv) { bv = l3; best = 3; }
        int pos = atomicAdd(&g_cnt[best], 1);
        g_idx[best * BT + pos] = row;
    }
}

// ---------------- tf32 mma GEMM, cp.async double-buffered ----------------
// C[M,N] = A[M,K] * B[N,K]^T. Block 128x128x32, 8 warps (2x4), warp 64x32.
// smem: 2 stages x (As[128][36] + Bs[128][36]) = 73728 bytes (dynamic).
#define GBM 128
#define GBN 128
#define GBK 32
#define GLD 36
#define GEMM_SMEM (4 * 128 * GLD * 4)

__global__ __launch_bounds__(256) void gemm_tf32(
    const float* __restrict__ A, const float* __restrict__ Bw, float* __restrict__ C,
    int M, int N, int K,
    const float* __restrict__ bias, const float* __restrict__ res,
    int relu, int use_idx, long wstride) {
    extern __shared__ float sm[];
    float* buf[2][2];
    buf[0][0] = sm;                         // As stage 0
    buf[0][1] = sm + 128 * GLD;             // Bs stage 0
    buf[1][0] = sm + 2 * 128 * GLD;         // As stage 1
    buf[1][1] = sm + 3 * 128 * GLD;         // Bs stage 1
    unsigned sbase = (unsigned)__cvta_generic_to_shared(sm);

    int e = blockIdx.z;
    const float* Bm = Bw + (long)e * wstride;
    int Mz = M;
    const int* rowmap = nullptr;
    if (use_idx) { Mz = g_cnt[e]; rowmap = g_idx + e * BT; }
    int i0 = blockIdx.y * GBM;
    if (i0 >= Mz) return;
    int j0 = blockIdx.x * GBN;

    int tid = threadIdx.x;
    int warp = tid >> 5, lane = tid & 31;
    int wm = warp >> 2, wn = warp & 3;
    int lg = lane >> 2, lr = lane & 3;

    // per-slice gathered A rows (same every k-tile)
    int arows[4]; int asz[4];
    int ldrow = tid >> 3, ldc4 = tid & 7;   // with it-offset below
#pragma unroll
    for (int it = 0; it < 4; it++) {
        int r = (tid + it * 256) >> 3;
        int pos = i0 + r;
        bool v = pos < Mz;
        asz[it] = v ? 16 : 0;
        arows[it] = rowmap ? (v ? rowmap[pos] : 0) : pos;
    }
    (void)ldrow; (void)ldc4;

    float acc[4][4][4];
#pragma unroll
    for (int mi = 0; mi < 4; mi++)
#pragma unroll
        for (int ni = 0; ni < 4; ni++)
#pragma unroll
            for (int q = 0; q < 4; q++) acc[mi][ni][q] = 0.f;

    int KT = K / GBK;

    // issue tile 0 into stage 0
    {
        unsigned adst = sbase;
        unsigned bdst = sbase + 128 * GLD * 4;
#pragma unroll
        for (int it = 0; it < 4; it++) {
            int f = tid + it * 256;
            int r = f >> 3, c4 = f & 7;
            cp_async16(adst + (r * GLD + c4 * 4) * 4, A + (long)arows[it] * K + c4 * 4, asz[it]);
            cp_async16(bdst + (r * GLD + c4 * 4) * 4, Bm + (long)(j0 + r) * K + c4 * 4, 16);
        }
        cp_commit();
    }

    for (int kt = 0; kt < KT; kt++) {
        cp_wait0();
        __syncthreads();                     // tile kt visible; all warps past compute(kt-1)
        if (kt + 1 < KT) {
            int nb = (kt + 1) & 1;
            int k0 = (kt + 1) * GBK;
            unsigned adst = sbase + (nb * 2) * 128 * GLD * 4;
            unsigned bdst = sbase + (nb * 2 + 1) * 128 * GLD * 4;
#pragma unroll
            for (int it = 0; it < 4; it++) {
                int f = tid + it * 256;
                int r = f >> 3, c4 = f & 7;
                cp_async16(adst + (r * GLD + c4 * 4) * 4, A + (long)arows[it] * K + k0 + c4 * 4, asz[it]);
                cp_async16(bdst + (r * GLD + c4 * 4) * 4, Bm + (long)(j0 + r) * K + k0 + c4 * 4, 16);
            }
            cp_commit();
        }
        const float* Asb = buf[kt & 1][0];
        const float* Bsb = buf[kt & 1][1];
#pragma unroll
        for (int kk = 0; kk < 4; kk++) {
            unsigned af[4][4], bf[4][2];
#pragma unroll
            for (int mi = 0; mi < 4; mi++) {
                int r0 = wm * 64 + mi * 16 + lg;
                af[mi][0] = f2tf(Asb[r0 * GLD + kk * 8 + lr]);
                af[mi][1] = f2tf(Asb[(r0 + 8) * GLD + kk * 8 + lr]);
                af[mi][2] = f2tf(Asb[r0 * GLD + kk * 8 + lr + 4]);
                af[mi][3] = f2tf(Asb[(r0 + 8) * GLD + kk * 8 + lr + 4]);
            }
#pragma unroll
            for (int ni = 0; ni < 4; ni++) {
                int c0 = wn * 32 + ni * 8 + lg;
                bf[ni][0] = f2tf(Bsb[c0 * GLD + kk * 8 + lr]);
                bf[ni][1] = f2tf(Bsb[c0 * GLD + kk * 8 + lr + 4]);
            }
#pragma unroll
            for (int mi = 0; mi < 4; mi++)
#pragma unroll
                for (int ni = 0; ni < 4; ni++)
                    mma_tf32(acc[mi][ni], af[mi], bf[ni][0], bf[ni][1]);
        }
    }

    // direct epilogue from registers
#pragma unroll
    for (int mi = 0; mi < 4; mi++) {
        int pos0 = i0 + wm * 64 + mi * 16 + lg;
        int pos1 = pos0 + 8;
        bool v0 = pos0 < Mz, v1 = pos1 < Mz;
        int cr0 = v0 ? (rowmap ? rowmap[pos0] : pos0) : 0;
        int cr1 = v1 ? (rowmap ? rowmap[pos1] : pos1) : 0;
#pragma unroll
        for (int ni = 0; ni < 4; ni++) {
            int col = j0 + wn * 32 + ni * 8 + lr * 2;
            float b0v = 0.f, b1v = 0.f;
            if (bias) { b0v = bias[(long)e * N + col]; b1v = bias[(long)e * N + col + 1]; }
            if (v0) {
                float x0 = acc[mi][ni][0] + b0v, x1 = acc[mi][ni][1] + b1v;
                if (relu) { x0 = fmaxf(x0, 0.f); x1 = fmaxf(x1, 0.f); }
                if (res) { x0 += res[(long)cr0 * N + col]; x1 += res[(long)cr0 * N + col + 1]; }
                *(float2*)&C[(long)cr0 * N + col] = make_float2(x0, x1);
            }
            if (v1) {
                float x0 = acc[mi][ni][2] + b0v, x1 = acc[mi][ni][3] + b1v;
                if (relu) { x0 = fmaxf(x0, 0.f); x1 = fmaxf(x1, 0.f); }
                if (res) { x0 += res[(long)cr1 * N + col]; x1 += res[(long)cr1 * N + col + 1]; }
                *(float2*)&C[(long)cr1 * N + col] = make_float2(x0, x1);
            }
        }
    }
}

// ---------------- fused flash attention (tf32 mma, online softmax, causal) ----------------
#define FA_LD 68
#define FA_SMEM (3 * 64 * FA_LD * 4)

__global__ __launch_bounds__(128) void flash_attn_kernel(
    const float* __restrict__ Q, const float* __restrict__ Kg,
    const float* __restrict__ Vg, float* __restrict__ O) {
    extern __shared__ float sm[];
    float* Ks = sm;
    float* Vs = sm + 64 * FA_LD;
    float* Ps = sm + 2 * 64 * FA_LD;

    int qt = blockIdx.x;
    int z  = blockIdx.y;
    int b  = z >> 4, h = z & 15;
    int q0 = qt * 64;
    int tid = threadIdx.x, warp = tid >> 5, lane = tid & 31;
    int lg = lane >> 2, lr = lane & 3;

    const float* Qb = Q  + (long)(b * Tdim) * DM + h * HD;
    const float* Kb = Kg + (long)(b * Tdim) * DM + h * HD;
    const float* Vb = Vg + (long)(b * Tdim) * DM + h * HD;

    for (int it = tid; it < 64 * 16; it += 128) {
        int r = it >> 4, c4 = it & 15;
        *(float4*)&Ps[r * FA_LD + c4 * 4] = *(const float4*)(Qb + (long)(q0 + r) * DM + c4 * 4);
    }
    __syncthreads();
    unsigned qa[8][4];
    int rlo = warp * 16 + lg;
#pragma unroll
    for (int ks = 0; ks < 8; ks++) {
        qa[ks][0] = f2tf(Ps[(rlo)     * FA_LD + ks * 8 + lr]);
        qa[ks][1] = f2tf(Ps[(rlo + 8) * FA_LD + ks * 8 + lr]);
        qa[ks][2] = f2tf(Ps[(rlo)     * FA_LD + ks * 8 + lr + 4]);
        qa[ks][3] = f2tf(Ps[(rlo + 8) * FA_LD + ks * 8 + lr + 4]);
    }

    float o[8][4];
#pragma unroll
    for (int nf = 0; nf < 8; nf++)
#pragma unroll
        for (int e = 0; e < 4; e++) o[nf][e] = 0.f;
    float m_lo = -1e30f, m_hi = -1e30f, l_lo = 0.f, l_hi = 0.f;

    int row_lo = q0 + warp * 16 + lg;
    int row_hi = row_lo + 8;

    for (int kc = 0; kc <= qt; kc++) {
        __syncthreads();
        for (int it = tid; it < 64 * 16; it += 128) {
            int r = it >> 4, c4 = it & 15;
            *(float4*)&Ks[r * FA_LD + c4 * 4] = *(const float4*)(Kb + (long)(kc * 64 + r) * DM + c4 * 4);
            *(float4*)&Vs[r * FA_LD + c4 * 4] = *(const float4*)(Vb + (long)(kc * 64 + r) * DM + c4 * 4);
        }
        __syncthreads();

        float s[8][4];
#pragma unroll
        for (int nf = 0; nf < 8; nf++)
#pragma unroll
            for (int e = 0; e < 4; e++) s[nf][e] = 0.f;
#pragma unroll
        for (int ks = 0; ks < 8; ks++) {
#pragma unroll
            for (int nf = 0; nf < 8; nf++) {
                unsigned b0 = f2tf(Ks[(nf * 8 + lg) * FA_LD + ks * 8 + lr]);
                unsigned b1 = f2tf(Ks[(nf * 8 + lg) * FA_LD + ks * 8 + lr + 4]);
                mma_tf32(s[nf], qa[ks], b0, b1);
            }
        }

        int colbase = kc * 64 + lr * 2;
#pragma unroll
        for (int nf = 0; nf < 8; nf++) {
            int c0 = colbase + nf * 8;
            s[nf][0] = (c0     <= row_lo) ? s[nf][0] * 0.125f : -1e30f;
            s[nf][1] = (c0 + 1 <= row_lo) ? s[nf][1] * 0.125f : -1e30f;
            s[nf][2] = (c0     <= row_hi) ? s[nf][2] * 0.125f : -1e30f;
            s[nf][3] = (c0 + 1 <= row_hi) ? s[nf][3] * 0.125f : -1e30f;
        }

        float cm_lo = -1e30f, cm_hi = -1e30f;
#pragma unroll
        for (int nf = 0; nf < 8; nf++) {
            cm_lo = fmaxf(cm_lo, fmaxf(s[nf][0], s[nf][1]));
            cm_hi = fmaxf(cm_hi, fmaxf(s[nf][2], s[nf][3]));
        }
        cm_lo = fmaxf(cm_lo, __shfl_xor_sync(0xffffffffu, cm_lo, 1));
        cm_lo = fmaxf(cm_lo, __shfl_xor_sync(0xffffffffu, cm_lo, 2));
        cm_hi = fmaxf(cm_hi, __shfl_xor_sync(0xffffffffu, cm_hi, 1));
        cm_hi = fmaxf(cm_hi, __shfl_xor_sync(0xffffffffu, cm_hi, 2));

        float nm_lo = fmaxf(m_lo, cm_lo), nm_hi = fmaxf(m_hi, cm_hi);
        float al_lo = __expf(m_lo - nm_lo), al_hi = __expf(m_hi - nm_hi);
        m_lo = nm_lo; m_hi = nm_hi;

        float ps_lo = 0.f, ps_hi = 0.f;
#pragma unroll
        for (int nf = 0; nf < 8; nf++) {
            s[nf][0] = __expf(s[nf][0] - m_lo);
            s[nf][1] = __expf(s[nf][1] - m_lo);
            s[nf][2] = __expf(s[nf][2] - m_hi);
            s[nf][3] = __expf(s[nf][3] - m_hi);
            ps_lo += s[nf][0] + s[nf][1];
            ps_hi += s[nf][2] + s[nf][3];
        }
        ps_lo += __shfl_xor_sync(0xffffffffu, ps_lo, 1);
        ps_lo += __shfl_xor_sync(0xffffffffu, ps_lo, 2);
        ps_hi += __shfl_xor_sync(0xffffffffu, ps_hi, 1);
        ps_hi += __shfl_xor_sync(0xffffffffu, ps_hi, 2);
        l_lo = l_lo * al_lo + ps_lo;
        l_hi = l_hi * al_hi + ps_hi;

#pragma unroll
        for (int nf = 0; nf < 8; nf++) {
            o[nf][0] *= al_lo; o[nf][1] *= al_lo;
            o[nf][2] *= al_hi; o[nf][3] *= al_hi;
        }

        int prl = warp * 16 + lg;
#pragma unroll
        for (int nf = 0; nf < 8; nf++) {
            Ps[(prl)     * FA_LD + nf * 8 + lr * 2]     = s[nf][0];
            Ps[(prl)     * FA_LD + nf * 8 + lr * 2 + 1] = s[nf][1];
            Ps[(prl + 8) * FA_LD + nf * 8 + lr * 2]     = s[nf][2];
            Ps[(prl + 8) * FA_LD + nf * 8 + lr * 2 + 1] = s[nf][3];
        }
        __syncwarp();

#pragma unroll
        for (int ks = 0; ks < 8; ks++) {
            unsigned pa[4];
            pa[0] = f2tf(Ps[(prl)     * FA_LD + ks * 8 + lr]);
            pa[1] = f2tf(Ps[(prl + 8) * FA_LD + ks * 8 + lr]);
            pa[2] = f2tf(Ps[(prl)     * FA_LD + ks * 8 + lr + 4]);
            pa[3] = f2tf(Ps[(prl + 8) * FA_LD + ks * 8 + lr + 4]);
#pragma unroll
            for (int nf = 0; nf < 8; nf++) {
                unsigned b0 = f2tf(Vs[(ks * 8 + lr)     * FA_LD + nf * 8 + lg]);
                unsigned b1 = f2tf(Vs[(ks * 8 + lr + 4) * FA_LD + nf * 8 + lg]);
                mma_tf32(o[nf], pa, b0, b1);
            }
        }
    }

    float inv_lo = 1.f / l_lo, inv_hi = 1.f / l_hi;
    long out_lo = (long)(b * Tdim + row_lo) * DM + h * HD;
    long out_hi = (long)(b * Tdim + row_hi) * DM + h * HD;
#pragma unroll
    for (int nf = 0; nf < 8; nf++) {
        int c = nf * 8 + lr * 2;
        *(float2*)&O[out_lo + c] = make_float2(o[nf][0] * inv_lo, o[nf][1] * inv_lo);
        *(float2*)&O[out_hi + c] = make_float2(o[nf][2] * inv_hi, o[nf][3] * inv_hi);
    }
}

// ---------------- launch ----------------
extern "C" void kernel_launch(void* const* d_in, const int* in_sizes, int n_in,
                              void* d_out, int out_size) {
    const float* x       = (const float*)d_in[0];
    const float* norm1_w = (const float*)d_in[1];
    const float* norm2_w = (const float*)d_in[2];
    const float* Wq      = (const float*)d_in[3];
    const float* Wdkv    = (const float*)d_in[4];
    const float* Wuk     = (const float*)d_in[5];
    const float* Wuv     = (const float*)d_in[6];
    const float* Wo      = (const float*)d_in[7];
    const float* ln_g    = (const float*)d_in[8];
    const float* ln_b    = (const float*)d_in[9];
    const float* gate_w  = (const float*)d_in[10];
    const float* gate_b  = (const float*)d_in[11];
    const float* W1      = (const float*)d_in[12];
    const float* b1      = (const float*)d_in[13];
    const float* W2      = (const float*)d_in[14];
    const float* b2      = (const float*)d_in[15];
    float* out = (float*)d_out;

    float *p_xn, *p_q, *p_lat, *p_k, *p_v, *p_attn, *p_x1, *p_xn2, *p_h;
    cudaGetSymbolAddress((void**)&p_xn,  g_xn);
    cudaGetSymbolAddress((void**)&p_q,   g_q);
    cudaGetSymbolAddress((void**)&p_lat, g_lat);
    cudaGetSymbolAddress((void**)&p_k,   g_k);
    cudaGetSymbolAddress((void**)&p_v,   g_v);
    cudaGetSymbolAddress((void**)&p_attn,g_attn);
    cudaGetSymbolAddress((void**)&p_x1,  g_x1);
    cudaGetSymbolAddress((void**)&p_xn2, g_xn2);
    cudaGetSymbolAddress((void**)&p_h,   g_h);

    cudaFuncSetAttribute(flash_attn_kernel, cudaFuncAttributeMaxDynamicSharedMemorySize, FA_SMEM);
    cudaFuncSetAttribute(gemm_tf32, cudaFuncAttributeMaxDynamicSharedMemorySize, GEMM_SMEM);

    // 1. xn = rmsnorm(x)
    rmsnorm_kernel<<<BT, 256>>>(x, norm1_w, p_xn);
    // 2. q = xn @ Wq^T
    gemm_tf32<<<dim3(DM/128, BT/128, 1), 256, GEMM_SMEM>>>(p_xn, Wq, p_q, BT, DM, DM, nullptr, nullptr, 0, 0, 0);
    // 3. lat = layernorm(xn @ Wdkv^T)
    gemm_tf32<<<dim3(KVL/128, BT/128, 1), 256, GEMM_SMEM>>>(p_xn, Wdkv, p_lat, BT, KVL, DM, nullptr, nullptr, 0, 0, 0);
    layernorm_kernel<<<BT, 256>>>(p_lat, ln_g, ln_b);
    // 4. k, v
    gemm_tf32<<<dim3(DM/128, BT/128, 1), 256, GEMM_SMEM>>>(p_lat, Wuk, p_k, BT, DM, KVL, nullptr, nullptr, 0, 0, 0);
    gemm_tf32<<<dim3(DM/128, BT/128, 1), 256, GEMM_SMEM>>>(p_lat, Wuv, p_v, BT, DM, KVL, nullptr, nullptr, 0, 0, 0);
    // 5. RoPE on q, k
    rope_kernel<<<4096, 256>>>(p_q);
    rope_kernel<<<4096, 256>>>(p_k);
    // 6. fused flash attention
    flash_attn_kernel<<<dim3(Tdim/64, 32), 128, FA_SMEM>>>(p_q, p_k, p_v, p_attn);
    // 7. x1 = x + attn @ Wo^T
    gemm_tf32<<<dim3(DM/128, BT/128, 1), 256, GEMM_SMEM>>>(p_attn, Wo, p_x1, BT, DM, DM, nullptr, x, 0, 0, 0);
    // 8. xn2 = rmsnorm(x1)
    rmsnorm_kernel<<<BT, 256>>>(p_x1, norm2_w, p_xn2);
    // 9. gating
    zero_cnt_kernel<<<1, 32>>>();
    gate_kernel<<<BT, 128>>>(p_xn2, gate_w, gate_b);
    // 10. MoE expert GEMMs
    gemm_tf32<<<dim3(DH/128, BT/128, NE), 256, GEMM_SMEM>>>(p_xn2, W1, p_h, BT, DH, DM, b1, nullptr, 1, 1, (long)DH * DM);
    gemm_tf32<<<dim3(DM/128, BT/128, NE), 256, GEMM_SMEM>>>(p_h, W2, out, BT, DM, DH, b2, p_x1, 0, 1, (long)DM * DH);
    (void)in_sizes; (void)n_in; (void)out_size;
}